// round 13
// baseline (speedup 1.0000x reference)
#include <cuda_runtime.h>
#include <math.h>
#include <stdint.h>

// Problem constants
#define NTOK 32768      // 8 * 4096 tokens
#define DIN  1536       // D + DC
#define DH   3072       // 2 * din
#define NE   64         // experts
#define DI   1024       // D
#define DCND 512        // DC

// GEMM1: 24 column-blocks of 128; first TCOLS tensor path, rest SIMT.
#define TCOLS  14
#define KC     16
#define NCHUNK (DIN / KC)        // 96
#define SSTR   20                // smem row stride (floats): gID*20+tig all-distinct mod 32
#define TILE_F (128 * SSTR)      // 2560 floats per tile
#define STAGE_F (4 * TILE_F)     // Ahi,Alo,Bhi,Blo: 10240 floats (40KB)
#define SMEM1_BYTES (2 * STAGE_F * 4)   // 81920 B (2 stages); SIMT path uses prefix

// Scratch
static __device__ float g_h[(size_t)NTOK * DH];          // gelu(X@W1^T)
static __device__ float g_xhi[(size_t)NTOK * DIN];       // tf32-hi of X
static __device__ float g_xlo[(size_t)NTOK * DIN];       // tf32-lo of X
static __device__ float g_w1hi[(size_t)DH * DIN];
static __device__ float g_w1lo[(size_t)DH * DIN];

__device__ __forceinline__ float gelu_exact(float x) {
    return 0.5f * x * (1.0f + erff(x * 0.7071067811865475f));
}

__device__ __forceinline__ void tf32_split(float x, float& h, float& l) {
    uint32_t t;
    asm("cvt.rna.tf32.f32 %0, %1;" : "=r"(t) : "f"(x));
    h = __uint_as_float(t);
    float r = x - h;
    asm("cvt.rna.tf32.f32 %0, %1;" : "=r"(t) : "f"(r));
    l = __uint_as_float(t);
}

__device__ __forceinline__ void mma1688(float c[4], const uint32_t a[4],
                                        uint32_t b0, uint32_t b1) {
    asm volatile(
        "mma.sync.aligned.m16n8k8.row.col.f32.tf32.tf32.f32 "
        "{%0,%1,%2,%3}, {%4,%5,%6,%7}, {%8,%9}, {%0,%1,%2,%3};"
        : "+f"(c[0]), "+f"(c[1]), "+f"(c[2]), "+f"(c[3])
        : "r"(a[0]), "r"(a[1]), "r"(a[2]), "r"(a[3]), "r"(b0), "r"(b1));
}

// ---------------------------------------------------------------------------
// Pre-split kernels: X = concat(inp,cond) and W1 into tf32 hi/lo planes.
// ---------------------------------------------------------------------------
__global__ void k_split_x(const float* __restrict__ inp, const float* __restrict__ cnd)
{
    const int row = blockIdx.x;                 // 0..NTOK-1
    const int c4  = threadIdx.x;                // 0..383 (float4 index)
    const int col = c4 * 4;
    float4 v;
    if (col < DI) v = *(const float4*)(inp + (size_t)row * DI + col);
    else          v = *(const float4*)(cnd + (size_t)row * DCND + (col - DI));
    float4 h, l;
    tf32_split(v.x, h.x, l.x); tf32_split(v.y, h.y, l.y);
    tf32_split(v.z, h.z, l.z); tf32_split(v.w, h.w, l.w);
    *(float4*)(g_xhi + (size_t)row * DIN + col) = h;
    *(float4*)(g_xlo + (size_t)row * DIN + col) = l;
}

__global__ void k_split_w(const float* __restrict__ W1)
{
    const int row = blockIdx.x;                 // 0..DH-1
    const int col = threadIdx.x * 4;
    float4 v = *(const float4*)(W1 + (size_t)row * DIN + col);
    float4 h, l;
    tf32_split(v.x, h.x, l.x); tf32_split(v.y, h.y, l.y);
    tf32_split(v.z, h.z, l.z); tf32_split(v.w, h.w, l.w);
    *(float4*)(g_w1hi + (size_t)row * DIN + col) = h;
    *(float4*)(g_w1lo + (size_t)row * DIN + col) = l;
}

// cp.async one K-chunk of pre-split tiles: Ahi,Alo (tokens) + Bhi,Blo (W1 rows)
__device__ __forceinline__ void cp_chunk16(float* st, int c, int tid, int nblk, int mblk)
{
    const int kbase = c * KC;
    const uint32_t s0 = (uint32_t)__cvta_generic_to_shared(st);
#pragma unroll
    for (int it = 0; it < 8; ++it) {
        const int idx  = tid + it * 256;        // 0..2047
        const int tile = idx >> 9;              // 0..3
        const int rem  = idx & 511;
        const int row  = rem >> 2;              // 0..127
        const int g    = rem & 3;               // 16B granule in row
        const int col  = kbase + g * 4;
        const float* src;
        if      (tile == 0) src = g_xhi  + (size_t)(nblk + row) * DIN + col;
        else if (tile == 1) src = g_xlo  + (size_t)(nblk + row) * DIN + col;
        else if (tile == 2) src = g_w1hi + (size_t)(mblk + row) * DIN + col;
        else                src = g_w1lo + (size_t)(mblk + row) * DIN + col;
        const uint32_t off = (uint32_t)(tile * TILE_F + row * SSTR + g * 4) * 4;
        asm volatile("cp.async.cg.shared.global [%0], [%1], 16;" :: "r"(s0 + off), "l"(src));
    }
}

// ---------------------------------------------------------------------------
// GEMM1 hybrid v2: tensor CTAs (no splits, no STS, lean regs) + SIMT CTAs.
// ---------------------------------------------------------------------------
extern "C" __global__ void __launch_bounds__(256, 2)
k_gemm1_hyb(const float* __restrict__ inp,
            const float* __restrict__ cnd,
            const float* __restrict__ W1)
{
    extern __shared__ float sm[];
    const int tid  = threadIdx.x;
    const int mblk = blockIdx.x * 128;
    const int nblk = blockIdx.y * 128;

    if (blockIdx.x < TCOLS) {
        // ================= tensor path (3xTF32, pre-split operands) ==========
        const int lane = tid & 31;
        const int wid  = tid >> 5;
        const int wm   = wid & 1;
        const int wn   = wid >> 1;
        const int gID  = lane >> 2;
        const int tig  = lane & 3;

        float acc[4][4][4];
#pragma unroll
        for (int mt = 0; mt < 4; mt++)
#pragma unroll
            for (int nt = 0; nt < 4; nt++)
#pragma unroll
                for (int q = 0; q < 4; q++) acc[mt][nt][q] = 0.f;

        cp_chunk16(sm, 0, tid, nblk, mblk);
        asm volatile("cp.async.commit_group;" ::: "memory");

        for (int c = 0; c < NCHUNK; ++c) {
            const int buf = c & 1;
            if (c + 1 < NCHUNK) {
                cp_chunk16(sm + ((c + 1) & 1) * STAGE_F, c + 1, tid, nblk, mblk);
                asm volatile("cp.async.commit_group;" ::: "memory");
                asm volatile("cp.async.wait_group 1;" ::: "memory");
            } else {
                asm volatile("cp.async.wait_group 0;" ::: "memory");
            }
            __syncthreads();

            const float* Ahi = sm + buf * STAGE_F;
            const float* Alo = Ahi + TILE_F;
            const float* Bhi = Ahi + 2 * TILE_F;
            const float* Blo = Ahi + 3 * TILE_F;
#pragma unroll
            for (int ks = 0; ks < 2; ++ks) {
                const int kk = ks * 8 + tig;
                uint32_t ah[4][4], al[4][4];
#pragma unroll
                for (int mt = 0; mt < 4; ++mt) {
                    const int r0 = wm * 64 + mt * 16 + gID;
                    ah[mt][0] = __float_as_uint(Ahi[r0 * SSTR + kk]);
                    ah[mt][1] = __float_as_uint(Ahi[(r0 + 8) * SSTR + kk]);
                    ah[mt][2] = __float_as_uint(Ahi[r0 * SSTR + kk + 4]);
                    ah[mt][3] = __float_as_uint(Ahi[(r0 + 8) * SSTR + kk + 4]);
                    al[mt][0] = __float_as_uint(Alo[r0 * SSTR + kk]);
                    al[mt][1] = __float_as_uint(Alo[(r0 + 8) * SSTR + kk]);
                    al[mt][2] = __float_as_uint(Alo[r0 * SSTR + kk + 4]);
                    al[mt][3] = __float_as_uint(Alo[(r0 + 8) * SSTR + kk + 4]);
                }
#pragma unroll
                for (int nt = 0; nt < 4; ++nt) {
                    const int nr = wn * 32 + nt * 8 + gID;
                    const uint32_t bh0 = __float_as_uint(Bhi[nr * SSTR + kk]);
                    const uint32_t bh1 = __float_as_uint(Bhi[nr * SSTR + kk + 4]);
                    const uint32_t bl0 = __float_as_uint(Blo[nr * SSTR + kk]);
                    const uint32_t bl1 = __float_as_uint(Blo[nr * SSTR + kk + 4]);
#pragma unroll
                    for (int mt = 0; mt < 4; ++mt)
                        mma1688(acc[mt][nt], ah[mt], bh0, bh1);   // hi*hi
#pragma unroll
                    for (int mt = 0; mt < 4; ++mt)
                        mma1688(acc[mt][nt], ah[mt], bl0, bl1);   // hi*lo
#pragma unroll
                    for (int mt = 0; mt < 4; ++mt)
                        mma1688(acc[mt][nt], al[mt], bh0, bh1);   // lo*hi
                }
            }
            __syncthreads();
        }

#pragma unroll
        for (int mt = 0; mt < 4; ++mt) {
            const int row0 = nblk + wm * 64 + mt * 16 + gID;
#pragma unroll
            for (int nt = 0; nt < 4; ++nt) {
                const int col = mblk + wn * 32 + nt * 8 + tig * 2;
                float2 v0, v1;
                v0.x = gelu_exact(acc[mt][nt][0]);
                v0.y = gelu_exact(acc[mt][nt][1]);
                v1.x = gelu_exact(acc[mt][nt][2]);
                v1.y = gelu_exact(acc[mt][nt][3]);
                *(float2*)(g_h + (size_t)row0 * DH + col)       = v0;
                *(float2*)(g_h + (size_t)(row0 + 8) * DH + col) = v1;
            }
        }
    } else {
        // ================= SIMT fp32 path (R3-proven SGEMM) =================
        float (*As)[8][132] = (float (*)[8][132])sm;                 // [2][8][132]
        float (*Bs)[8][132] = (float (*)[8][132])(sm + 2 * 8 * 132); // [2][8][132]

        const int tx   = tid & 15;
        const int ty   = tid >> 4;
        const int lrow = tid >> 1;
        const int lk4  = (tid & 1) << 2;

        float acc[8][8];
#pragma unroll
        for (int i = 0; i < 8; i++)
#pragma unroll
            for (int j = 0; j < 8; j++) acc[i][j] = 0.f;

        const size_t arow_i = (size_t)(nblk + lrow) * DI;
        const size_t arow_c = (size_t)(nblk + lrow) * DCND;
        const size_t brow   = (size_t)(mblk + lrow) * DIN;

        float4 av, bv;
        av = *(const float4*)(inp + arow_i + lk4);
        bv = *(const float4*)(W1  + brow   + lk4);
        As[0][lk4+0][lrow] = av.x; As[0][lk4+1][lrow] = av.y;
        As[0][lk4+2][lrow] = av.z; As[0][lk4+3][lrow] = av.w;
        Bs[0][lk4+0][lrow] = bv.x; Bs[0][lk4+1][lrow] = bv.y;
        Bs[0][lk4+2][lrow] = bv.z; Bs[0][lk4+3][lrow] = bv.w;
        __syncthreads();

        int buf = 0;
        for (int k0 = 8; k0 <= DIN; k0 += 8) {
            if (k0 < DIN) {
                const int kk = k0 + lk4;
                if (kk < DI) av = *(const float4*)(inp + arow_i + kk);
                else         av = *(const float4*)(cnd + arow_c + (kk - DI));
                bv = *(const float4*)(W1 + brow + kk);
            }
#pragma unroll
            for (int k = 0; k < 8; k++) {
                float4 a0 = *(const float4*)&As[buf][k][ty*8];
                float4 a1 = *(const float4*)&As[buf][k][ty*8+4];
                float4 b0 = *(const float4*)&Bs[buf][k][tx*8];
                float4 b1 = *(const float4*)&Bs[buf][k][tx*8+4];
                float a[8] = {a0.x,a0.y,a0.z,a0.w,a1.x,a1.y,a1.z,a1.w};
                float b[8] = {b0.x,b0.y,b0.z,b0.w,b1.x,b1.y,b1.z,b1.w};
#pragma unroll
                for (int i = 0; i < 8; i++)
#pragma unroll
                    for (int j = 0; j < 8; j++)
                        acc[i][j] = fmaf(a[i], b[j], acc[i][j]);
            }
            if (k0 < DIN) {
                const int nb = buf ^ 1;
                As[nb][lk4+0][lrow] = av.x; As[nb][lk4+1][lrow] = av.y;
                As[nb][lk4+2][lrow] = av.z; As[nb][lk4+3][lrow] = av.w;
                Bs[nb][lk4+0][lrow] = bv.x; Bs[nb][lk4+1][lrow] = bv.y;
                Bs[nb][lk4+2][lrow] = bv.z; Bs[nb][lk4+3][lrow] = bv.w;
                buf = nb;
            }
            __syncthreads();
        }

#pragma unroll
        for (int i = 0; i < 8; i++) {
            const int n = nblk + ty*8 + i;
            float* dst = g_h + (size_t)n * DH + mblk + tx*8;
            float4 o0, o1;
            o0.x = gelu_exact(acc[i][0]); o0.y = gelu_exact(acc[i][1]);
            o0.z = gelu_exact(acc[i][2]); o0.w = gelu_exact(acc[i][3]);
            o1.x = gelu_exact(acc[i][4]); o1.y = gelu_exact(acc[i][5]);
            o1.z = gelu_exact(acc[i][6]); o1.w = gelu_exact(acc[i][7]);
            *(float4*)(dst)     = o0;
            *(float4*)(dst + 4) = o1;
        }
    }
}

// ---------------------------------------------------------------------------
// Kernel 2 (unchanged, passing): logits + softmax + top-2 + outputs
// ---------------------------------------------------------------------------
__global__ __launch_bounds__(256, 2)
void k_gemm2(const float* __restrict__ W2, float* __restrict__ out)
{
    __shared__ float As[2][8][132];
    __shared__ float Bs[2][8][68];
    __shared__ float lg[128][65];

    const int nblk = blockIdx.x * 128;
    const int tid  = threadIdx.x;
    const int tx   = tid & 15;
    const int ty   = tid >> 4;
    const int lrow = tid >> 1;
    const int lk4  = (tid & 1) << 2;

    float acc[8][4];
#pragma unroll
    for (int i = 0; i < 8; i++)
#pragma unroll
        for (int j = 0; j < 4; j++) acc[i][j] = 0.f;

    const size_t arow = (size_t)(nblk + lrow) * DH;
    const int    erow = tid >> 1;
    const size_t brow = (size_t)erow * DH;

    float4 av, bv;
    av = *(const float4*)(g_h + arow + lk4);
    if (tid < 128) bv = *(const float4*)(W2 + brow + lk4);
    As[0][lk4+0][lrow] = av.x; As[0][lk4+1][lrow] = av.y;
    As[0][lk4+2][lrow] = av.z; As[0][lk4+3][lrow] = av.w;
    if (tid < 128) {
        Bs[0][lk4+0][erow] = bv.x; Bs[0][lk4+1][erow] = bv.y;
        Bs[0][lk4+2][erow] = bv.z; Bs[0][lk4+3][erow] = bv.w;
    }
    __syncthreads();

    int buf = 0;
    for (int k0 = 8; k0 <= DH; k0 += 8) {
        if (k0 < DH) {
            av = *(const float4*)(g_h + arow + k0 + lk4);
            if (tid < 128) bv = *(const float4*)(W2 + brow + k0 + lk4);
        }
#pragma unroll
        for (int k = 0; k < 8; k++) {
            float4 a0 = *(const float4*)&As[buf][k][ty*8];
            float4 a1 = *(const float4*)&As[buf][k][ty*8+4];
            float4 b0 = *(const float4*)&Bs[buf][k][tx*4];
            float a[8] = {a0.x,a0.y,a0.z,a0.w,a1.x,a1.y,a1.z,a1.w};
            float b[4] = {b0.x,b0.y,b0.z,b0.w};
#pragma unroll
            for (int i = 0; i < 8; i++)
#pragma unroll
                for (int j = 0; j < 4; j++)
                    acc[i][j] = fmaf(a[i], b[j], acc[i][j]);
        }
        if (k0 < DH) {
            const int nb = buf ^ 1;
            As[nb][lk4+0][lrow] = av.x; As[nb][lk4+1][lrow] = av.y;
            As[nb][lk4+2][lrow] = av.z; As[nb][lk4+3][lrow] = av.w;
            if (tid < 128) {
                Bs[nb][lk4+0][erow] = bv.x; Bs[nb][lk4+1][erow] = bv.y;
                Bs[nb][lk4+2][erow] = bv.z; Bs[nb][lk4+3][erow] = bv.w;
            }
            buf = nb;
        }
        __syncthreads();
    }

#pragma unroll
    for (int i = 0; i < 8; i++)
#pragma unroll
        for (int j = 0; j < 4; j++)
            lg[ty*8+i][tx*4+j] = acc[i][j];
    __syncthreads();

    if (tid < 128) {
        const int r = tid;
        const int n = nblk + r;

        float m1 = -1e30f; int i1 = 0;
#pragma unroll
        for (int e = 0; e < NE; e++) {
            float v = lg[r][e];
            if (v > m1) { m1 = v; i1 = e; }
        }
        float m2 = -1e30f; int i2 = 0;
#pragma unroll
        for (int e = 0; e < NE; e++) {
            if (e == i1) continue;
            float v = lg[r][e];
            if (v > m2) { m2 = v; i2 = e; }
        }
        float s = 0.f;
#pragma unroll
        for (int e = 0; e < NE; e++) s += expf(lg[r][e] - m1);
        const float inv = 1.0f / s;

        const float lo = 1e-9f, hi = 1.0f - 1e-9f;
        const float p1 = fminf(fmaxf(inv + lo, lo), hi);
        const float p2 = fminf(fmaxf(expf(m2 - m1) * inv + lo, lo), hi);
        const float rn = 1.0f / (p1 + p2);

        float* mask = out;
        float* ti   = out + (size_t)NTOK * NE;
        float* rp   = out + (size_t)NTOK * NE + (size_t)NTOK * 2;
        float* pr   = rp  + (size_t)NTOK * NE;

#pragma unroll
        for (int e = 0; e < NE; e++) {
            float v = expf(lg[r][e] - m1) * inv + lo;
            v = fminf(fmaxf(v, lo), hi);
            pr[(size_t)n * NE + e]   = v;
            mask[(size_t)n * NE + e] = (e == i1 || e == i2) ? 1.0f : 0.0f;
            rp[(size_t)n * NE + e]   = (e == i1) ? p1 * rn
                                     : (e == i2) ? p2 * rn : 0.0f;
        }
        ti[(size_t)n * 2 + 0] = (float)i1;
        ti[(size_t)n * 2 + 1] = (float)i2;
    }
}

// ---------------------------------------------------------------------------
extern "C" void kernel_launch(void* const* d_in, const int* in_sizes, int n_in,
                              void* d_out, int out_size)
{
    const float* inp = (const float*)d_in[0];   // [8,4096,1024]
    const float* cnd = (const float*)d_in[1];   // [8,4096,512]
    const float* W1  = (const float*)d_in[2];   // [3072,1536]
    const float* W2  = (const float*)d_in[3];   // [64,3072]
    float* out = (float*)d_out;

    cudaFuncSetAttribute(k_gemm1_hyb, cudaFuncAttributeMaxDynamicSharedMemorySize, SMEM1_BYTES);

    k_split_x<<<NTOK, 384>>>(inp, cnd);
    k_split_w<<<DH, 384>>>(W1);

    dim3 g1(DH / 128, NTOK / 128);   // 24 x 256 CTAs, mixed tensor/SIMT
    k_gemm1_hyb<<<g1, 256, SMEM1_BYTES>>>(inp, cnd, W1);
    k_gemm2<<<NTOK / 128, 256>>>(W2, out);
}

// round 14
// speedup vs baseline: 1.6814x; 1.6814x over previous
#include <cuda_runtime.h>
#include <cuda_fp16.h>
#include <math.h>
#include <stdint.h>

// Problem constants
#define NTOK 32768      // 8 * 4096 tokens
#define DIN  1536       // D + DC
#define DH   3072       // 2 * din
#define NE   64         // experts
#define DI   1024       // D
#define DCND 512        // DC

// GEMM1 tiling: CTA 128 tokens x 128 hcols, K-chunk 32, fp16x3 mma m16n8k16
#define KC      32
#define NCHUNK  (DIN / KC)      // 48
// Fragment-major fp16 smem:
// A: [mt(8)][ks(2)][plane(2)][lane(32)] x float4(=a0..a3 half2)   = 16384 B
// B: [nt(16)][ks(2)][lane(32)] x float4(=bhi0,bhi1,blo0,blo1)     = 16384 B
#define B_REGION 16384
#define STAGE_B  32768
#define SMEM1_BYTES (2 * STAGE_B)   // 65536
#define WSCALE   1024.0f            // exact pow2 pre-scale for W1 (fp16 denormal fix)
#define WDESCALE 0.0009765625f      // 2^-10

// Scratch for h = gelu(X @ W1^T)
static __device__ float g_h[(size_t)NTOK * DH];

__device__ __forceinline__ float gelu_exact(float x) {
    return 0.5f * x * (1.0f + erff(x * 0.7071067811865475f));
}

// Split (e0,e1) into packed half2 hi and half2 lo (residuals).
__device__ __forceinline__ void h2_split(float e0, float e1, uint32_t& hi, uint32_t& lo) {
    __half h0 = __float2half_rn(e0), h1 = __float2half_rn(e1);
    float r0 = e0 - __half2float(h0);
    float r1 = e1 - __half2float(h1);
    __half l0 = __float2half_rn(r0), l1 = __float2half_rn(r1);
    hi = ((uint32_t)__half_as_ushort(h1) << 16) | __half_as_ushort(h0);
    lo = ((uint32_t)__half_as_ushort(l1) << 16) | __half_as_ushort(l0);
}

__device__ __forceinline__ void mma16816(float c[4], const uint32_t a[4],
                                         uint32_t b0, uint32_t b1) {
    asm volatile(
        "mma.sync.aligned.m16n8k16.row.col.f32.f16.f16.f32 "
        "{%0,%1,%2,%3}, {%4,%5,%6,%7}, {%8,%9}, {%0,%1,%2,%3};"
        : "+f"(c[0]), "+f"(c[1]), "+f"(c[2]), "+f"(c[3])
        : "r"(a[0]), "r"(a[1]), "r"(a[2]), "r"(a[3]), "r"(b0), "r"(b1));
}

__device__ __forceinline__ void load_chunk_g1(
    int c, int tid, int nblk, int mblk,
    const float* __restrict__ inp, const float* __restrict__ cnd,
    const float* __restrict__ W1, float4 pa[4], float4 pb[4])
{
    const int kbase = c * KC;
#pragma unroll
    for (int it = 0; it < 4; ++it) {
        const int idx = tid + it * 256;
        const int row = idx >> 3, c4 = idx & 7;
        const int kk = kbase + c4 * 4;
        const float* asrc = (kk < DI)
            ? inp + (size_t)(nblk + row) * DI   + kk
            : cnd + (size_t)(nblk + row) * DCND + (kk - DI);
        pa[it] = *(const float4*)asrc;
        pb[it] = *(const float4*)(W1 + (size_t)(mblk + row) * DIN + kk);
    }
}

// Convert + store one chunk into fragment-major fp16 layout.
__device__ __forceinline__ void store_chunk_g1(
    char* base, int tid, const float4 pa[4], const float4 pb[4])
{
#pragma unroll
    for (int it = 0; it < 4; ++it) {
        const int idx = tid + it * 256;
        const int row = idx >> 3, c4 = idx & 7;
        // ---- A: token row, pairs p=2c4, 2c4+1 ----
        {
            const int mt = row >> 4, r16 = row & 15, g = r16 & 7, hb = r16 >> 3;
            const float4 v = pa[it];
#pragma unroll
            for (int sub = 0; sub < 2; ++sub) {
                const int p  = 2 * c4 + sub;
                const int ks = p >> 3, q = p & 7, t = q & 3, rh = q >> 2;
                const int reg = rh * 2 + hb, lane = g * 4 + t;
                uint32_t hi, lo;
                h2_split(sub ? v.z : v.x, sub ? v.w : v.y, hi, lo);
                char* blk = base + (((mt * 2 + ks) * 2) * 32 + lane) * 16 + reg * 4;
                *(uint32_t*)(blk)            = hi;   // plane 0
                *(uint32_t*)(blk + 32 * 16)  = lo;   // plane 1 (next 512B block)
            }
        }
        // ---- B: W1 row = n col, scaled by 2^10 ----
        {
            const int nt = row >> 3, g = row & 7;
            const float4 v = pb[it];
#pragma unroll
            for (int sub = 0; sub < 2; ++sub) {
                const int p  = 2 * c4 + sub;
                const int ks = p >> 3, q = p & 7, t = q & 3, bi = q >> 2;
                const int lane = g * 4 + t;
                uint32_t hi, lo;
                h2_split((sub ? v.z : v.x) * WSCALE, (sub ? v.w : v.y) * WSCALE, hi, lo);
                char* blk = base + B_REGION + ((nt * 2 + ks) * 32 + lane) * 16;
                *(uint32_t*)(blk + bi * 4)       = hi;   // slots 0,1
                *(uint32_t*)(blk + (2 + bi) * 4) = lo;   // slots 2,3
            }
        }
    }
}

// ---------------------------------------------------------------------------
// GEMM1 (mma.sync f16 m16n8k16, 3-pass split): g_h = gelu(X @ W1^T)
// ---------------------------------------------------------------------------
extern "C" __global__ void __launch_bounds__(256)
k_gemm1_mma(const float* __restrict__ inp,
            const float* __restrict__ cnd,
            const float* __restrict__ W1)
{
    extern __shared__ char sm[];

    const int tid  = threadIdx.x;
    const int lane = tid & 31;
    const int wid  = tid >> 5;
    const int wm   = wid & 1;          // 0..1 : 64-token half
    const int wn   = wid >> 1;         // 0..3 : 32-hcol slice
    const int gID  = lane >> 2;        // 0..7
    const int tig  = lane & 3;         // 0..3
    const int mblk = blockIdx.x * 128; // hcol base
    const int nblk = blockIdx.y * 128; // token base

    float acc[4][4][4];
#pragma unroll
    for (int mt = 0; mt < 4; mt++)
#pragma unroll
        for (int nt = 0; nt < 4; nt++)
#pragma unroll
            for (int q = 0; q < 4; q++) acc[mt][nt][q] = 0.f;

    float4 pa[4], pb[4];

    // prologue: chunk 0 -> stage 0
    load_chunk_g1(0, tid, nblk, mblk, inp, cnd, W1, pa, pb);
    store_chunk_g1(sm, tid, pa, pb);
    __syncthreads();

    for (int c = 0; c < NCHUNK; ++c) {
        const int buf = c & 1;
        const bool more = (c + 1) < NCHUNK;
        if (more) load_chunk_g1(c + 1, tid, nblk, mblk, inp, cnd, W1, pa, pb);

        const char* st = sm + buf * STAGE_B;
#pragma unroll
        for (int ks = 0; ks < 2; ++ks) {
            uint32_t ah[4][4], al[4][4], bb[4][4];
#pragma unroll
            for (int mt = 0; mt < 4; ++mt) {
                const char* blk = st + ((((wm * 4 + mt) * 2 + ks) * 2) * 32 + lane) * 16;
                uint4 vh = *(const uint4*)(blk);
                uint4 vl = *(const uint4*)(blk + 32 * 16);
                ah[mt][0] = vh.x; ah[mt][1] = vh.y; ah[mt][2] = vh.z; ah[mt][3] = vh.w;
                al[mt][0] = vl.x; al[mt][1] = vl.y; al[mt][2] = vl.z; al[mt][3] = vl.w;
            }
#pragma unroll
            for (int nt = 0; nt < 4; ++nt) {
                const char* blk = st + B_REGION + (((wn * 4 + nt) * 2 + ks) * 32 + lane) * 16;
                uint4 v = *(const uint4*)blk;
                bb[nt][0] = v.x; bb[nt][1] = v.y; bb[nt][2] = v.z; bb[nt][3] = v.w;
            }
            // pass-major: 16 independent accumulators between reuses
#pragma unroll
            for (int mt = 0; mt < 4; ++mt)
#pragma unroll
                for (int nt = 0; nt < 4; ++nt)
                    mma16816(acc[mt][nt], ah[mt], bb[nt][0], bb[nt][1]);   // hi*hi
#pragma unroll
            for (int mt = 0; mt < 4; ++mt)
#pragma unroll
                for (int nt = 0; nt < 4; ++nt)
                    mma16816(acc[mt][nt], ah[mt], bb[nt][2], bb[nt][3]);   // hi*lo
#pragma unroll
            for (int mt = 0; mt < 4; ++mt)
#pragma unroll
                for (int nt = 0; nt < 4; ++nt)
                    mma16816(acc[mt][nt], al[mt], bb[nt][0], bb[nt][1]);   // lo*hi
        }

        if (more) store_chunk_g1(sm + ((c + 1) & 1) * STAGE_B, tid, pa, pb);
        __syncthreads();
    }

    // ---- epilogue: descale (W1 was x1024), GELU, store ----
#pragma unroll
    for (int mt = 0; mt < 4; ++mt) {
        const int row0 = nblk + wm * 64 + mt * 16 + gID;
#pragma unroll
        for (int nt = 0; nt < 4; ++nt) {
            const int col = mblk + wn * 32 + nt * 8 + tig * 2;
            float2 v0, v1;
            v0.x = gelu_exact(acc[mt][nt][0] * WDESCALE);
            v0.y = gelu_exact(acc[mt][nt][1] * WDESCALE);
            v1.x = gelu_exact(acc[mt][nt][2] * WDESCALE);
            v1.y = gelu_exact(acc[mt][nt][3] * WDESCALE);
            *(float2*)(g_h + (size_t)row0 * DH + col)       = v0;
            *(float2*)(g_h + (size_t)(row0 + 8) * DH + col) = v1;
        }
    }
}

// ---------------------------------------------------------------------------
// Kernel 2 (unchanged, passing): logits + softmax + top-2 + outputs
// ---------------------------------------------------------------------------
__global__ __launch_bounds__(256, 2)
void k_gemm2(const float* __restrict__ W2, float* __restrict__ out)
{
    __shared__ float As[2][8][132];
    __shared__ float Bs[2][8][68];
    __shared__ float lg[128][65];

    const int nblk = blockIdx.x * 128;
    const int tid  = threadIdx.x;
    const int tx   = tid & 15;
    const int ty   = tid >> 4;
    const int lrow = tid >> 1;
    const int lk4  = (tid & 1) << 2;

    float acc[8][4];
#pragma unroll
    for (int i = 0; i < 8; i++)
#pragma unroll
        for (int j = 0; j < 4; j++) acc[i][j] = 0.f;

    const size_t arow = (size_t)(nblk + lrow) * DH;
    const int    erow = tid >> 1;
    const size_t brow = (size_t)erow * DH;

    float4 av, bv;
    av = *(const float4*)(g_h + arow + lk4);
    if (tid < 128) bv = *(const float4*)(W2 + brow + lk4);
    As[0][lk4+0][lrow] = av.x; As[0][lk4+1][lrow] = av.y;
    As[0][lk4+2][lrow] = av.z; As[0][lk4+3][lrow] = av.w;
    if (tid < 128) {
        Bs[0][lk4+0][erow] = bv.x; Bs[0][lk4+1][erow] = bv.y;
        Bs[0][lk4+2][erow] = bv.z; Bs[0][lk4+3][erow] = bv.w;
    }
    __syncthreads();

    int buf = 0;
    for (int k0 = 8; k0 <= DH; k0 += 8) {
        if (k0 < DH) {
            av = *(const float4*)(g_h + arow + k0 + lk4);
            if (tid < 128) bv = *(const float4*)(W2 + brow + k0 + lk4);
        }
#pragma unroll
        for (int k = 0; k < 8; k++) {
            float4 a0 = *(const float4*)&As[buf][k][ty*8];
            float4 a1 = *(const float4*)&As[buf][k][ty*8+4];
            float4 b0 = *(const float4*)&Bs[buf][k][tx*4];
            float a[8] = {a0.x,a0.y,a0.z,a0.w,a1.x,a1.y,a1.z,a1.w};
            float b[4] = {b0.x,b0.y,b0.z,b0.w};
#pragma unroll
            for (int i = 0; i < 8; i++)
#pragma unroll
                for (int j = 0; j < 4; j++)
                    acc[i][j] = fmaf(a[i], b[j], acc[i][j]);
        }
        if (k0 < DH) {
            const int nb = buf ^ 1;
            As[nb][lk4+0][lrow] = av.x; As[nb][lk4+1][lrow] = av.y;
            As[nb][lk4+2][lrow] = av.z; As[nb][lk4+3][lrow] = av.w;
            if (tid < 128) {
                Bs[nb][lk4+0][erow] = bv.x; Bs[nb][lk4+1][erow] = bv.y;
                Bs[nb][lk4+2][erow] = bv.z; Bs[nb][lk4+3][erow] = bv.w;
            }
            buf = nb;
        }
        __syncthreads();
    }

#pragma unroll
    for (int i = 0; i < 8; i++)
#pragma unroll
        for (int j = 0; j < 4; j++)
            lg[ty*8+i][tx*4+j] = acc[i][j];
    __syncthreads();

    if (tid < 128) {
        const int r = tid;
        const int n = nblk + r;

        float m1 = -1e30f; int i1 = 0;
#pragma unroll
        for (int e = 0; e < NE; e++) {
            float v = lg[r][e];
            if (v > m1) { m1 = v; i1 = e; }
        }
        float m2 = -1e30f; int i2 = 0;
#pragma unroll
        for (int e = 0; e < NE; e++) {
            if (e == i1) continue;
            float v = lg[r][e];
            if (v > m2) { m2 = v; i2 = e; }
        }
        float s = 0.f;
#pragma unroll
        for (int e = 0; e < NE; e++) s += expf(lg[r][e] - m1);
        const float inv = 1.0f / s;

        const float lo = 1e-9f, hi = 1.0f - 1e-9f;
        const float p1 = fminf(fmaxf(inv + lo, lo), hi);
        const float p2 = fminf(fmaxf(expf(m2 - m1) * inv + lo, lo), hi);
        const float rn = 1.0f / (p1 + p2);

        float* mask = out;
        float* ti   = out + (size_t)NTOK * NE;
        float* rp   = out + (size_t)NTOK * NE + (size_t)NTOK * 2;
        float* pr   = rp  + (size_t)NTOK * NE;

#pragma unroll
        for (int e = 0; e < NE; e++) {
            float v = expf(lg[r][e] - m1) * inv + lo;
            v = fminf(fmaxf(v, lo), hi);
            pr[(size_t)n * NE + e]   = v;
            mask[(size_t)n * NE + e] = (e == i1 || e == i2) ? 1.0f : 0.0f;
            rp[(size_t)n * NE + e]   = (e == i1) ? p1 * rn
                                     : (e == i2) ? p2 * rn : 0.0f;
        }
        ti[(size_t)n * 2 + 0] = (float)i1;
        ti[(size_t)n * 2 + 1] = (float)i2;
    }
}

// ---------------------------------------------------------------------------
extern "C" void kernel_launch(void* const* d_in, const int* in_sizes, int n_in,
                              void* d_out, int out_size)
{
    const float* inp = (const float*)d_in[0];   // [8,4096,1024]
    const float* cnd = (const float*)d_in[1];   // [8,4096,512]
    const float* W1  = (const float*)d_in[2];   // [3072,1536]
    const float* W2  = (const float*)d_in[3];   // [64,3072]
    float* out = (float*)d_out;

    cudaFuncSetAttribute(k_gemm1_mma, cudaFuncAttributeMaxDynamicSharedMemorySize, SMEM1_BYTES);

    dim3 g1(DH / 128, NTOK / 128);   // 24 x 256 CTAs
    k_gemm1_mma<<<g1, 256, SMEM1_BYTES>>>(inp, cnd, W1);
    k_gemm2<<<NTOK / 128, 256>>>(W2, out);
}

// round 15
// speedup vs baseline: 2.3051x; 1.3709x over previous
#include <cuda_runtime.h>
#include <cuda_fp16.h>
#include <math.h>
#include <stdint.h>

// Problem constants
#define NTOK 32768      // 8 * 4096 tokens
#define DIN  1536       // D + DC
#define DH   3072       // 2 * din
#define NE   64         // experts
#define DI   1024       // D
#define DCND 512        // DC

// GEMM1 tiling: CTA 128 tokens x 128 hcols, K-chunk 32, fp16x3 mma m16n8k16
#define KC      32
#define NCHUNK  (DIN / KC)      // 48
// Fragment-major fp16 block layout (per 128-row x 32-k chunk), 16384 B each:
// A: [mt(8)][ks(2)][plane(2)][lane(32)] x 16B   (planes: hi, lo)
// B: [nt(16)][ks(2)][lane(32)] x 16B            (16B = bhi0,bhi1,blo0,blo1)
#define BLK_U32  4096           // uint32 per 16KB block
#define B_REGION 16384
#define STAGE_B  32768
#define NSTAGE   3
#define SMEM1_BYTES (NSTAGE * STAGE_B)   // 98304
#define WSCALE   1024.0f            // exact pow2 pre-scale for W1 (fp16 denormal fix)
#define WDESCALE 0.0009765625f      // 2^-10

// Scratch
static __device__ float    g_h[(size_t)NTOK * DH];
static __device__ uint32_t g_xsp[(size_t)256 * NCHUNK * BLK_U32];  // 196 MB
static __device__ uint32_t g_wsp[(size_t)24  * NCHUNK * BLK_U32];  // 18.9 MB

__device__ __forceinline__ float gelu_exact(float x) {
    return 0.5f * x * (1.0f + erff(x * 0.7071067811865475f));
}

__device__ __forceinline__ void h2_split(float e0, float e1, uint32_t& hi, uint32_t& lo) {
    __half h0 = __float2half_rn(e0), h1 = __float2half_rn(e1);
    float r0 = e0 - __half2float(h0);
    float r1 = e1 - __half2float(h1);
    __half l0 = __float2half_rn(r0), l1 = __float2half_rn(r1);
    hi = ((uint32_t)__half_as_ushort(h1) << 16) | __half_as_ushort(h0);
    lo = ((uint32_t)__half_as_ushort(l1) << 16) | __half_as_ushort(l0);
}

__device__ __forceinline__ void mma16816(float c[4], const uint32_t a[4],
                                         uint32_t b0, uint32_t b1) {
    asm volatile(
        "mma.sync.aligned.m16n8k16.row.col.f32.f16.f16.f32 "
        "{%0,%1,%2,%3}, {%4,%5,%6,%7}, {%8,%9}, {%0,%1,%2,%3};"
        : "+f"(c[0]), "+f"(c[1]), "+f"(c[2]), "+f"(c[3])
        : "r"(a[0]), "r"(a[1]), "r"(a[2]), "r"(a[3]), "r"(b0), "r"(b1));
}

// ---------------------------------------------------------------------------
// Pre-split kernels -> fragment-major fp16 hi/lo blocks in gmem.
// ---------------------------------------------------------------------------
__global__ void k_presplit_x(const float* __restrict__ inp, const float* __restrict__ cnd)
{
    const int c   = blockIdx.x;           // chunk
    const int tb  = blockIdx.y;           // token block
    const int tid = threadIdx.x;
    const int nblk  = tb * 128;
    const int kbase = c * KC;
    char* base = (char*)(g_xsp + ((size_t)tb * NCHUNK + c) * BLK_U32);
#pragma unroll
    for (int it = 0; it < 4; ++it) {
        const int idx = tid + it * 256;
        const int row = idx >> 3, c4 = idx & 7;
        const int kk = kbase + c4 * 4;
        const float* src = (kk < DI)
            ? inp + (size_t)(nblk + row) * DI   + kk
            : cnd + (size_t)(nblk + row) * DCND + (kk - DI);
        const float4 v = *(const float4*)src;
        const int mt = row >> 4, r16 = row & 15, g = r16 & 7, hb = r16 >> 3;
#pragma unroll
        for (int sub = 0; sub < 2; ++sub) {
            const int p  = 2 * c4 + sub;
            const int ks = p >> 3, q = p & 7, t = q & 3, rh = q >> 2;
            const int reg = rh * 2 + hb, lane = g * 4 + t;
            uint32_t hi, lo;
            h2_split(sub ? v.z : v.x, sub ? v.w : v.y, hi, lo);
            char* blk = base + (((mt * 2 + ks) * 2) * 32 + lane) * 16 + reg * 4;
            *(uint32_t*)(blk)           = hi;   // plane 0
            *(uint32_t*)(blk + 32 * 16) = lo;   // plane 1
        }
    }
}

__global__ void k_presplit_w(const float* __restrict__ W1)
{
    const int c   = blockIdx.x;           // chunk
    const int cb  = blockIdx.y;           // column block
    const int tid = threadIdx.x;
    const int mblk  = cb * 128;
    const int kbase = c * KC;
    char* base = (char*)(g_wsp + ((size_t)cb * NCHUNK + c) * BLK_U32);
#pragma unroll
    for (int it = 0; it < 4; ++it) {
        const int idx = tid + it * 256;
        const int row = idx >> 3, c4 = idx & 7;
        const int kk = kbase + c4 * 4;
        const float4 v = *(const float4*)(W1 + (size_t)(mblk + row) * DIN + kk);
        const int nt = row >> 3, g = row & 7;
#pragma unroll
        for (int sub = 0; sub < 2; ++sub) {
            const int p  = 2 * c4 + sub;
            const int ks = p >> 3, q = p & 7, t = q & 3, bi = q >> 2;
            const int lane = g * 4 + t;
            uint32_t hi, lo;
            h2_split((sub ? v.z : v.x) * WSCALE, (sub ? v.w : v.y) * WSCALE, hi, lo);
            char* blk = base + ((nt * 2 + ks) * 32 + lane) * 16;
            *(uint32_t*)(blk + bi * 4)       = hi;
            *(uint32_t*)(blk + (2 + bi) * 4) = lo;
        }
    }
}

// cp.async one chunk's A+B blocks (contiguous 16KB each) into a stage.
__device__ __forceinline__ void cp_chunk(char* stage, int tid, int tb, int cb, int c)
{
    const uint32_t dA = (uint32_t)__cvta_generic_to_shared(stage);
    const char* sA = (const char*)(g_xsp + ((size_t)tb * NCHUNK + c) * BLK_U32);
    const char* sB = (const char*)(g_wsp + ((size_t)cb * NCHUNK + c) * BLK_U32);
#pragma unroll
    for (int it = 0; it < 4; ++it) {
        const uint32_t off = (uint32_t)(tid + it * 256) * 16;
        asm volatile("cp.async.cg.shared.global [%0], [%1], 16;"
                     :: "r"(dA + off), "l"(sA + off));
        asm volatile("cp.async.cg.shared.global [%0], [%1], 16;"
                     :: "r"(dA + B_REGION + off), "l"(sB + off));
    }
}

// ---------------------------------------------------------------------------
// GEMM1 (mma.sync f16 m16n8k16, 3-pass): lean mainloop, pre-split operands.
// ---------------------------------------------------------------------------
extern "C" __global__ void __launch_bounds__(256, 1)
k_gemm1_mma()
{
    extern __shared__ char sm[];

    const int tid  = threadIdx.x;
    const int lane = tid & 31;
    const int wid  = tid >> 5;
    const int wm   = wid & 1;
    const int wn   = wid >> 1;
    const int gID  = lane >> 2;
    const int tig  = lane & 3;
    const int cb   = blockIdx.x;          // column block (0..23)
    const int tb   = blockIdx.y;          // token block  (0..255)
    const int mblk = cb * 128;
    const int nblk = tb * 128;

    float acc[4][4][4];
#pragma unroll
    for (int mt = 0; mt < 4; mt++)
#pragma unroll
        for (int nt = 0; nt < 4; nt++)
#pragma unroll
            for (int q = 0; q < 4; q++) acc[mt][nt][q] = 0.f;

    // prologue: chunks 0,1 in flight
    cp_chunk(sm, tid, tb, cb, 0);
    asm volatile("cp.async.commit_group;" ::: "memory");
    cp_chunk(sm + STAGE_B, tid, tb, cb, 1);
    asm volatile("cp.async.commit_group;" ::: "memory");

    for (int c = 0; c < NCHUNK; ++c) {
        if (c + 1 < NCHUNK)
            asm volatile("cp.async.wait_group 1;" ::: "memory");
        else
            asm volatile("cp.async.wait_group 0;" ::: "memory");
        __syncthreads();

        const char* st = sm + (c % NSTAGE) * STAGE_B;
#pragma unroll
        for (int ks = 0; ks < 2; ++ks) {
            uint32_t ah[4][4], al[4][4], bb[4][4];
#pragma unroll
            for (int mt = 0; mt < 4; ++mt) {
                const char* blk = st + ((((wm * 4 + mt) * 2 + ks) * 2) * 32 + lane) * 16;
                uint4 vh = *(const uint4*)(blk);
                uint4 vl = *(const uint4*)(blk + 32 * 16);
                ah[mt][0] = vh.x; ah[mt][1] = vh.y; ah[mt][2] = vh.z; ah[mt][3] = vh.w;
                al[mt][0] = vl.x; al[mt][1] = vl.y; al[mt][2] = vl.z; al[mt][3] = vl.w;
            }
#pragma unroll
            for (int nt = 0; nt < 4; ++nt) {
                const char* blk = st + B_REGION + (((wn * 4 + nt) * 2 + ks) * 32 + lane) * 16;
                uint4 v = *(const uint4*)blk;
                bb[nt][0] = v.x; bb[nt][1] = v.y; bb[nt][2] = v.z; bb[nt][3] = v.w;
            }
#pragma unroll
            for (int mt = 0; mt < 4; ++mt)
#pragma unroll
                for (int nt = 0; nt < 4; ++nt)
                    mma16816(acc[mt][nt], ah[mt], bb[nt][0], bb[nt][1]);   // hi*hi
#pragma unroll
            for (int mt = 0; mt < 4; ++mt)
#pragma unroll
                for (int nt = 0; nt < 4; ++nt)
                    mma16816(acc[mt][nt], ah[mt], bb[nt][2], bb[nt][3]);   // hi*lo
#pragma unroll
            for (int mt = 0; mt < 4; ++mt)
#pragma unroll
                for (int nt = 0; nt < 4; ++nt)
                    mma16816(acc[mt][nt], al[mt], bb[nt][0], bb[nt][1]);   // lo*hi
        }
        __syncthreads();   // all warps done with stage (c % NSTAGE)

        if (c + 2 < NCHUNK) {
            cp_chunk(sm + ((c + 2) % NSTAGE) * STAGE_B, tid, tb, cb, c + 2);
            asm volatile("cp.async.commit_group;" ::: "memory");
        }
    }

    // ---- epilogue: descale (W1 was x1024), GELU, store ----
#pragma unroll
    for (int mt = 0; mt < 4; ++mt) {
        const int row0 = nblk + wm * 64 + mt * 16 + gID;
#pragma unroll
        for (int nt = 0; nt < 4; ++nt) {
            const int col = mblk + wn * 32 + nt * 8 + tig * 2;
            float2 v0, v1;
            v0.x = gelu_exact(acc[mt][nt][0] * WDESCALE);
            v0.y = gelu_exact(acc[mt][nt][1] * WDESCALE);
            v1.x = gelu_exact(acc[mt][nt][2] * WDESCALE);
            v1.y = gelu_exact(acc[mt][nt][3] * WDESCALE);
            *(float2*)(g_h + (size_t)row0 * DH + col)       = v0;
            *(float2*)(g_h + (size_t)(row0 + 8) * DH + col) = v1;
        }
    }
}

// ---------------------------------------------------------------------------
// Kernel 2 (unchanged, passing): logits + softmax + top-2 + outputs
// ---------------------------------------------------------------------------
__global__ __launch_bounds__(256, 2)
void k_gemm2(const float* __restrict__ W2, float* __restrict__ out)
{
    __shared__ float As[2][8][132];
    __shared__ float Bs[2][8][68];
    __shared__ float lg[128][65];

    const int nblk = blockIdx.x * 128;
    const int tid  = threadIdx.x;
    const int tx   = tid & 15;
    const int ty   = tid >> 4;
    const int lrow = tid >> 1;
    const int lk4  = (tid & 1) << 2;

    float acc[8][4];
#pragma unroll
    for (int i = 0; i < 8; i++)
#pragma unroll
        for (int j = 0; j < 4; j++) acc[i][j] = 0.f;

    const size_t arow = (size_t)(nblk + lrow) * DH;
    const int    erow = tid >> 1;
    const size_t brow = (size_t)erow * DH;

    float4 av, bv;
    av = *(const float4*)(g_h + arow + lk4);
    if (tid < 128) bv = *(const float4*)(W2 + brow + lk4);
    As[0][lk4+0][lrow] = av.x; As[0][lk4+1][lrow] = av.y;
    As[0][lk4+2][lrow] = av.z; As[0][lk4+3][lrow] = av.w;
    if (tid < 128) {
        Bs[0][lk4+0][erow] = bv.x; Bs[0][lk4+1][erow] = bv.y;
        Bs[0][lk4+2][erow] = bv.z; Bs[0][lk4+3][erow] = bv.w;
    }
    __syncthreads();

    int buf = 0;
    for (int k0 = 8; k0 <= DH; k0 += 8) {
        if (k0 < DH) {
            av = *(const float4*)(g_h + arow + k0 + lk4);
            if (tid < 128) bv = *(const float4*)(W2 + brow + k0 + lk4);
        }
#pragma unroll
        for (int k = 0; k < 8; k++) {
            float4 a0 = *(const float4*)&As[buf][k][ty*8];
            float4 a1 = *(const float4*)&As[buf][k][ty*8+4];
            float4 b0 = *(const float4*)&Bs[buf][k][tx*4];
            float a[8] = {a0.x,a0.y,a0.z,a0.w,a1.x,a1.y,a1.z,a1.w};
            float b[4] = {b0.x,b0.y,b0.z,b0.w};
#pragma unroll
            for (int i = 0; i < 8; i++)
#pragma unroll
                for (int j = 0; j < 4; j++)
                    acc[i][j] = fmaf(a[i], b[j], acc[i][j]);
        }
        if (k0 < DH) {
            const int nb = buf ^ 1;
            As[nb][lk4+0][lrow] = av.x; As[nb][lk4+1][lrow] = av.y;
            As[nb][lk4+2][lrow] = av.z; As[nb][lk4+3][lrow] = av.w;
            if (tid < 128) {
                Bs[nb][lk4+0][erow] = bv.x; Bs[nb][lk4+1][erow] = bv.y;
                Bs[nb][lk4+2][erow] = bv.z; Bs[nb][lk4+3][erow] = bv.w;
            }
            buf = nb;
        }
        __syncthreads();
    }

#pragma unroll
    for (int i = 0; i < 8; i++)
#pragma unroll
        for (int j = 0; j < 4; j++)
            lg[ty*8+i][tx*4+j] = acc[i][j];
    __syncthreads();

    if (tid < 128) {
        const int r = tid;
        const int n = nblk + r;

        float m1 = -1e30f; int i1 = 0;
#pragma unroll
        for (int e = 0; e < NE; e++) {
            float v = lg[r][e];
            if (v > m1) { m1 = v; i1 = e; }
        }
        float m2 = -1e30f; int i2 = 0;
#pragma unroll
        for (int e = 0; e < NE; e++) {
            if (e == i1) continue;
            float v = lg[r][e];
            if (v > m2) { m2 = v; i2 = e; }
        }
        float s = 0.f;
#pragma unroll
        for (int e = 0; e < NE; e++) s += expf(lg[r][e] - m1);
        const float inv = 1.0f / s;

        const float lo = 1e-9f, hi = 1.0f - 1e-9f;
        const float p1 = fminf(fmaxf(inv + lo, lo), hi);
        const float p2 = fminf(fmaxf(expf(m2 - m1) * inv + lo, lo), hi);
        const float rn = 1.0f / (p1 + p2);

        float* mask = out;
        float* ti   = out + (size_t)NTOK * NE;
        float* rp   = out + (size_t)NTOK * NE + (size_t)NTOK * 2;
        float* pr   = rp  + (size_t)NTOK * NE;

#pragma unroll
        for (int e = 0; e < NE; e++) {
            float v = expf(lg[r][e] - m1) * inv + lo;
            v = fminf(fmaxf(v, lo), hi);
            pr[(size_t)n * NE + e]   = v;
            mask[(size_t)n * NE + e] = (e == i1 || e == i2) ? 1.0f : 0.0f;
            rp[(size_t)n * NE + e]   = (e == i1) ? p1 * rn
                                     : (e == i2) ? p2 * rn : 0.0f;
        }
        ti[(size_t)n * 2 + 0] = (float)i1;
        ti[(size_t)n * 2 + 1] = (float)i2;
    }
}

// ---------------------------------------------------------------------------
extern "C" void kernel_launch(void* const* d_in, const int* in_sizes, int n_in,
                              void* d_out, int out_size)
{
    const float* inp = (const float*)d_in[0];   // [8,4096,1024]
    const float* cnd = (const float*)d_in[1];   // [8,4096,512]
    const float* W1  = (const float*)d_in[2];   // [3072,1536]
    const float* W2  = (const float*)d_in[3];   // [64,3072]
    float* out = (float*)d_out;

    cudaFuncSetAttribute(k_gemm1_mma, cudaFuncAttributeMaxDynamicSharedMemorySize, SMEM1_BYTES);

    dim3 gx(NCHUNK, 256);   // pre-split X
    k_presplit_x<<<gx, 256>>>(inp, cnd);
    dim3 gw(NCHUNK, 24);    // pre-split W1
    k_presplit_w<<<gw, 256>>>(W1);

    dim3 g1(DH / 128, NTOK / 128);   // 24 x 256 CTAs
    k_gemm1_mma<<<g1, 256, SMEM1_BYTES>>>();
    k_gemm2<<<NTOK / 128, 256>>>(W2, out);
}

// round 16
// speedup vs baseline: 2.4874x; 1.0791x over previous
#include <cuda_runtime.h>
#include <cuda_fp16.h>
#include <math.h>
#include <stdint.h>

// Problem constants
#define NTOK 32768      // 8 * 4096 tokens
#define DIN  1536       // D + DC
#define DH   3072       // 2 * din
#define NE   64         // experts
#define DI   1024       // D
#define DCND 512        // DC

#define KC      32
#define NCHUNK  (DIN / KC)      // 48  (GEMM1 K-chunks)
#define NCHUNK2 (DH / KC)       // 96  (GEMM2 K-chunks)
// Fragment-major fp16 block layouts:
// A-block (128 rows x 32 k): [mt2(8)][ks(2)][plane(2)][lane(32)] x 16B = 16384 B
// B-block (128 rows x 32 k): [nt(16)][ks(2)][lane(32)] x 16B           = 16384 B
// B2-block (64 rows x 32 k): [nt(8)][ks(2)][lane(32)] x 16B            = 8192 B
#define ABLK_U32  4096
#define BBLK2_U32 2048
#define B_REGION 16384
#define STAGE_B  32768
#define NSTAGE   3
#define SMEM1_BYTES (NSTAGE * STAGE_B)     // 98304
#define STAGE2_B 24576                      // 16KB A + 8KB B2
#define SMEM2_BYTES (NSTAGE * STAGE2_B)    // 73728
#define WSCALE   1024.0f        // W1 pre-scale 2^10
#define WDESCALE 0.0009765625f  // 2^-10
#define HSCALE   16.0f          // h pre-scale 2^4
#define W2SCALE  32.0f          // W2 pre-scale 2^5
#define DS2      0.001953125f   // 2^-9 (undo HSCALE*W2SCALE)

// Scratch
static __device__ uint32_t g_xsp[(size_t)256 * NCHUNK * ABLK_U32];    // 201 MB
static __device__ uint32_t g_wsp[(size_t)24  * NCHUNK * ABLK_U32];    // 18.9 MB
static __device__ uint32_t g_hsp[(size_t)256 * NCHUNK2 * ABLK_U32];   // 402.7 MB
static __device__ uint32_t g_w2sp[(size_t)NCHUNK2 * BBLK2_U32];       // 786 KB

__device__ __forceinline__ float gelu_exact(float x) {
    return 0.5f * x * (1.0f + erff(x * 0.7071067811865475f));
}

__device__ __forceinline__ void h2_split(float e0, float e1, uint32_t& hi, uint32_t& lo) {
    __half h0 = __float2half_rn(e0), h1 = __float2half_rn(e1);
    float r0 = e0 - __half2float(h0);
    float r1 = e1 - __half2float(h1);
    __half l0 = __float2half_rn(r0), l1 = __float2half_rn(r1);
    hi = ((uint32_t)__half_as_ushort(h1) << 16) | __half_as_ushort(h0);
    lo = ((uint32_t)__half_as_ushort(l1) << 16) | __half_as_ushort(l0);
}

__device__ __forceinline__ void mma16816(float c[4], const uint32_t a[4],
                                         uint32_t b0, uint32_t b1) {
    asm volatile(
        "mma.sync.aligned.m16n8k16.row.col.f32.f16.f16.f32 "
        "{%0,%1,%2,%3}, {%4,%5,%6,%7}, {%8,%9}, {%0,%1,%2,%3};"
        : "+f"(c[0]), "+f"(c[1]), "+f"(c[2]), "+f"(c[3])
        : "r"(a[0]), "r"(a[1]), "r"(a[2]), "r"(a[3]), "r"(b0), "r"(b1));
}

// ---------------------------------------------------------------------------
// Pre-split: X -> fragment-major A-blocks (smem-staged, coalesced out)
// ---------------------------------------------------------------------------
__global__ void k_presplit_x(const float* __restrict__ inp, const float* __restrict__ cnd)
{
    __shared__ uint32_t sb[ABLK_U32];
    const int c   = blockIdx.x;
    const int tb  = blockIdx.y;
    const int tid = threadIdx.x;
    const int nblk  = tb * 128;
    const int kbase = c * KC;
#pragma unroll
    for (int it = 0; it < 4; ++it) {
        const int idx = tid + it * 256;
        const int row = idx >> 3, c4 = idx & 7;
        const int kk = kbase + c4 * 4;
        const float* src = (kk < DI)
            ? inp + (size_t)(nblk + row) * DI   + kk
            : cnd + (size_t)(nblk + row) * DCND + (kk - DI);
        const float4 v = *(const float4*)src;
        const int mt = row >> 4, r16 = row & 15, g = r16 & 7, hb = r16 >> 3;
#pragma unroll
        for (int sub = 0; sub < 2; ++sub) {
            const int p  = 2 * c4 + sub;
            const int ks = p >> 3, q = p & 7, t = q & 3, rh = q >> 2;
            const int reg = rh * 2 + hb, lane = g * 4 + t;
            uint32_t hi, lo;
            h2_split(sub ? v.z : v.x, sub ? v.w : v.y, hi, lo);
            sb[(((mt * 2 + ks) * 2 + 0) * 32 + lane) * 4 + reg] = hi;
            sb[(((mt * 2 + ks) * 2 + 1) * 32 + lane) * 4 + reg] = lo;
        }
    }
    __syncthreads();
    uint4* dst = (uint4*)(g_xsp + ((size_t)tb * NCHUNK + c) * ABLK_U32);
    const uint4* s4 = (const uint4*)sb;
#pragma unroll
    for (int it = 0; it < 4; ++it)
        dst[tid + it * 256] = s4[tid + it * 256];
}

// Pre-split W1 -> B-blocks (scaled by 2^10)
__global__ void k_presplit_w(const float* __restrict__ W1)
{
    __shared__ uint32_t sb[ABLK_U32];
    const int c   = blockIdx.x;
    const int cb  = blockIdx.y;
    const int tid = threadIdx.x;
    const int mblk  = cb * 128;
    const int kbase = c * KC;
#pragma unroll
    for (int it = 0; it < 4; ++it) {
        const int idx = tid + it * 256;
        const int row = idx >> 3, c4 = idx & 7;
        const int kk = kbase + c4 * 4;
        const float4 v = *(const float4*)(W1 + (size_t)(mblk + row) * DIN + kk);
        const int nt = row >> 3, g = row & 7;
#pragma unroll
        for (int sub = 0; sub < 2; ++sub) {
            const int p  = 2 * c4 + sub;
            const int ks = p >> 3, q = p & 7, t = q & 3, bi = q >> 2;
            const int lane = g * 4 + t;
            uint32_t hi, lo;
            h2_split((sub ? v.z : v.x) * WSCALE, (sub ? v.w : v.y) * WSCALE, hi, lo);
            sb[((nt * 2 + ks) * 32 + lane) * 4 + bi]     = hi;
            sb[((nt * 2 + ks) * 32 + lane) * 4 + 2 + bi] = lo;
        }
    }
    __syncthreads();
    uint4* dst = (uint4*)(g_wsp + ((size_t)cb * NCHUNK + c) * ABLK_U32);
    const uint4* s4 = (const uint4*)sb;
#pragma unroll
    for (int it = 0; it < 4; ++it)
        dst[tid + it * 256] = s4[tid + it * 256];
}

// Pre-split W2 (64 x 3072, scaled by 2^5) -> B2-blocks. Tiny (1.5 MB).
__global__ void k_presplit_w2(const float* __restrict__ W2)
{
    __shared__ uint32_t sb[BBLK2_U32];
    const int c   = blockIdx.x;       // 0..95
    const int tid = threadIdx.x;
    const int kbase = c * KC;
#pragma unroll
    for (int it = 0; it < 2; ++it) {
        const int idx = tid + it * 256;      // 0..511
        const int row = idx >> 3, c4 = idx & 7;
        const float4 v = *(const float4*)(W2 + (size_t)row * DH + kbase + c4 * 4);
        const int nt = row >> 3, g = row & 7;
#pragma unroll
        for (int sub = 0; sub < 2; ++sub) {
            const int p  = 2 * c4 + sub;
            const int ks = p >> 3, q = p & 7, t = q & 3, bi = q >> 2;
            const int lane = g * 4 + t;
            uint32_t hi, lo;
            h2_split((sub ? v.z : v.x) * W2SCALE, (sub ? v.w : v.y) * W2SCALE, hi, lo);
            sb[((nt * 2 + ks) * 32 + lane) * 4 + bi]     = hi;
            sb[((nt * 2 + ks) * 32 + lane) * 4 + 2 + bi] = lo;
        }
    }
    __syncthreads();
    uint4* dst = (uint4*)(g_w2sp + (size_t)c * BBLK2_U32);
    const uint4* s4 = (const uint4*)sb;
#pragma unroll
    for (int it = 0; it < 2; ++it)
        dst[tid + it * 256] = s4[tid + it * 256];
}

// ---------------------------------------------------------------------------
// GEMM1: cp.async pre-split blocks; epilogue writes h pre-split (fragment-
// major A-blocks for GEMM2) via smem staging, fully coalesced.
// ---------------------------------------------------------------------------
__device__ __forceinline__ void cp_chunk(char* stage, int tid, int tb, int cb, int c)
{
    const uint32_t dA = (uint32_t)__cvta_generic_to_shared(stage);
    const char* sA = (const char*)(g_xsp + ((size_t)tb * NCHUNK + c) * ABLK_U32);
    const char* sB = (const char*)(g_wsp + ((size_t)cb * NCHUNK + c) * ABLK_U32);
#pragma unroll
    for (int it = 0; it < 4; ++it) {
        const uint32_t off = (uint32_t)(tid + it * 256) * 16;
        asm volatile("cp.async.cg.shared.global [%0], [%1], 16;"
                     :: "r"(dA + off), "l"(sA + off));
        asm volatile("cp.async.cg.shared.global [%0], [%1], 16;"
                     :: "r"(dA + B_REGION + off), "l"(sB + off));
    }
}

extern "C" __global__ void __launch_bounds__(256, 1)
k_gemm1_mma()
{
    extern __shared__ char sm[];

    const int tid  = threadIdx.x;
    const int lane = tid & 31;
    const int wid  = tid >> 5;
    const int wm   = wid & 1;
    const int wn   = wid >> 1;
    const int gID  = lane >> 2;
    const int tig  = lane & 3;
    const int cb   = blockIdx.x;          // 0..23
    const int tb   = blockIdx.y;          // 0..255

    float acc[4][4][4];
#pragma unroll
    for (int mt = 0; mt < 4; mt++)
#pragma unroll
        for (int nt = 0; nt < 4; nt++)
#pragma unroll
            for (int q = 0; q < 4; q++) acc[mt][nt][q] = 0.f;

    cp_chunk(sm, tid, tb, cb, 0);
    asm volatile("cp.async.commit_group;" ::: "memory");
    cp_chunk(sm + STAGE_B, tid, tb, cb, 1);
    asm volatile("cp.async.commit_group;" ::: "memory");

    for (int c = 0; c < NCHUNK; ++c) {
        if (c + 1 < NCHUNK)
            asm volatile("cp.async.wait_group 1;" ::: "memory");
        else
            asm volatile("cp.async.wait_group 0;" ::: "memory");
        __syncthreads();

        const char* st = sm + (c % NSTAGE) * STAGE_B;
#pragma unroll
        for (int ks = 0; ks < 2; ++ks) {
            uint32_t ah[4][4], al[4][4], bb[4][4];
#pragma unroll
            for (int mt = 0; mt < 4; ++mt) {
                const char* blk = st + ((((wm * 4 + mt) * 2 + ks) * 2) * 32 + lane) * 16;
                uint4 vh = *(const uint4*)(blk);
                uint4 vl = *(const uint4*)(blk + 32 * 16);
                ah[mt][0] = vh.x; ah[mt][1] = vh.y; ah[mt][2] = vh.z; ah[mt][3] = vh.w;
                al[mt][0] = vl.x; al[mt][1] = vl.y; al[mt][2] = vl.z; al[mt][3] = vl.w;
            }
#pragma unroll
            for (int nt = 0; nt < 4; ++nt) {
                const char* blk = st + B_REGION + (((wn * 4 + nt) * 2 + ks) * 32 + lane) * 16;
                uint4 v = *(const uint4*)blk;
                bb[nt][0] = v.x; bb[nt][1] = v.y; bb[nt][2] = v.z; bb[nt][3] = v.w;
            }
#pragma unroll
            for (int mt = 0; mt < 4; ++mt)
#pragma unroll
                for (int nt = 0; nt < 4; ++nt)
                    mma16816(acc[mt][nt], ah[mt], bb[nt][0], bb[nt][1]);
#pragma unroll
            for (int mt = 0; mt < 4; ++mt)
#pragma unroll
                for (int nt = 0; nt < 4; ++nt)
                    mma16816(acc[mt][nt], ah[mt], bb[nt][2], bb[nt][3]);
#pragma unroll
            for (int mt = 0; mt < 4; ++mt)
#pragma unroll
                for (int nt = 0; nt < 4; ++nt)
                    mma16816(acc[mt][nt], al[mt], bb[nt][0], bb[nt][1]);
        }
        __syncthreads();

        if (c + 2 < NCHUNK) {
            cp_chunk(sm + ((c + 2) % NSTAGE) * STAGE_B, tid, tb, cb, c + 2);
            asm volatile("cp.async.commit_group;" ::: "memory");
        }
    }

    // ---- epilogue: gelu -> h*16 split -> smem (4 A-blocks) -> coalesced out
    uint32_t* sb = (uint32_t*)sm;   // 64KB staging
#pragma unroll
    for (int mt = 0; mt < 4; ++mt) {
#pragma unroll
        for (int nt = 0; nt < 4; ++nt) {
            float h00 = gelu_exact(acc[mt][nt][0] * WDESCALE) * HSCALE;
            float h01 = gelu_exact(acc[mt][nt][1] * WDESCALE) * HSCALE;
            float h10 = gelu_exact(acc[mt][nt][2] * WDESCALE) * HSCALE;
            float h11 = gelu_exact(acc[mt][nt][3] * WDESCALE) * HSCALE;
            uint32_t hi0, lo0, hi1, lo1;
            h2_split(h00, h01, hi0, lo0);   // rows r0   (hb=0)
            h2_split(h10, h11, hi1, lo1);   // rows r0+8 (hb=1)
            const int mt2 = wm * 4 + mt;
            const int ks  = nt >> 1;
            const int rh  = nt & 1;
            const int ln  = gID * 4 + tig;
            const int p0  = wn * ABLK_U32 + (((mt2 * 2 + ks) * 2 + 0) * 32 + ln) * 4;
            const int p1  = wn * ABLK_U32 + (((mt2 * 2 + ks) * 2 + 1) * 32 + ln) * 4;
            sb[p0 + rh * 2 + 0] = hi0;
            sb[p0 + rh * 2 + 1] = hi1;
            sb[p1 + rh * 2 + 0] = lo0;
            sb[p1 + rh * 2 + 1] = lo1;
        }
    }
    __syncthreads();
    const uint4* s4 = (const uint4*)sb;
#pragma unroll
    for (int j = 0; j < 4; ++j) {
        uint4* dst = (uint4*)(g_hsp + ((size_t)tb * NCHUNK2 + cb * 4 + j) * ABLK_U32);
#pragma unroll
        for (int it = 0; it < 4; ++it)
            dst[tid + it * 256] = s4[j * 1024 + tid + it * 256];
    }
}

// ---------------------------------------------------------------------------
// GEMM2 (fp16x3 mma): logits from pre-split h/W2 + fused softmax/top-2.
// ---------------------------------------------------------------------------
__device__ __forceinline__ void cp_chunk2(char* stage, int tid, int tb, int c)
{
    const uint32_t dA = (uint32_t)__cvta_generic_to_shared(stage);
    const char* sA = (const char*)(g_hsp + ((size_t)tb * NCHUNK2 + c) * ABLK_U32);
    const char* sB = (const char*)(g_w2sp + (size_t)c * BBLK2_U32);
#pragma unroll
    for (int it = 0; it < 4; ++it) {
        const uint32_t off = (uint32_t)(tid + it * 256) * 16;
        asm volatile("cp.async.cg.shared.global [%0], [%1], 16;"
                     :: "r"(dA + off), "l"(sA + off));
    }
#pragma unroll
    for (int it = 0; it < 2; ++it) {
        const uint32_t off = (uint32_t)(tid + it * 256) * 16;
        asm volatile("cp.async.cg.shared.global [%0], [%1], 16;"
                     :: "r"(dA + B_REGION + off), "l"(sB + off));
    }
}

extern "C" __global__ void __launch_bounds__(256, 2)
k_gemm2_mma(float* __restrict__ out)
{
    extern __shared__ char sm[];

    const int tid  = threadIdx.x;
    const int lane = tid & 31;
    const int wid  = tid >> 5;
    const int wm   = wid & 3;          // 32-token quarter
    const int wn   = wid >> 2;         // 32-expert half
    const int gID  = lane >> 2;
    const int tig  = lane & 3;
    const int tb   = blockIdx.x;       // token block
    const int nblk = tb * 128;

    float acc[2][4][4];
#pragma unroll
    for (int mt = 0; mt < 2; mt++)
#pragma unroll
        for (int nt = 0; nt < 4; nt++)
#pragma unroll
            for (int q = 0; q < 4; q++) acc[mt][nt][q] = 0.f;

    cp_chunk2(sm, tid, tb, 0);
    asm volatile("cp.async.commit_group;" ::: "memory");
    cp_chunk2(sm + STAGE2_B, tid, tb, 1);
    asm volatile("cp.async.commit_group;" ::: "memory");

    for (int c = 0; c < NCHUNK2; ++c) {
        if (c + 1 < NCHUNK2)
            asm volatile("cp.async.wait_group 1;" ::: "memory");
        else
            asm volatile("cp.async.wait_group 0;" ::: "memory");
        __syncthreads();

        const char* st = sm + (c % NSTAGE) * STAGE2_B;
#pragma unroll
        for (int ks = 0; ks < 2; ++ks) {
            uint32_t ah[2][4], al[2][4], bb[4][4];
#pragma unroll
            for (int mt = 0; mt < 2; ++mt) {
                const char* blk = st + ((((wm * 2 + mt) * 2 + ks) * 2) * 32 + lane) * 16;
                uint4 vh = *(const uint4*)(blk);
                uint4 vl = *(const uint4*)(blk + 32 * 16);
                ah[mt][0] = vh.x; ah[mt][1] = vh.y; ah[mt][2] = vh.z; ah[mt][3] = vh.w;
                al[mt][0] = vl.x; al[mt][1] = vl.y; al[mt][2] = vl.z; al[mt][3] = vl.w;
            }
#pragma unroll
            for (int nt = 0; nt < 4; ++nt) {
                const char* blk = st + B_REGION + (((wn * 4 + nt) * 2 + ks) * 32 + lane) * 16;
                uint4 v = *(const uint4*)blk;
                bb[nt][0] = v.x; bb[nt][1] = v.y; bb[nt][2] = v.z; bb[nt][3] = v.w;
            }
#pragma unroll
            for (int mt = 0; mt < 2; ++mt)
#pragma unroll
                for (int nt = 0; nt < 4; ++nt)
                    mma16816(acc[mt][nt], ah[mt], bb[nt][0], bb[nt][1]);
#pragma unroll
            for (int mt = 0; mt < 2; ++mt)
#pragma unroll
                for (int nt = 0; nt < 4; ++nt)
                    mma16816(acc[mt][nt], ah[mt], bb[nt][2], bb[nt][3]);
#pragma unroll
            for (int mt = 0; mt < 2; ++mt)
#pragma unroll
                for (int nt = 0; nt < 4; ++nt)
                    mma16816(acc[mt][nt], al[mt], bb[nt][0], bb[nt][1]);
        }
        __syncthreads();

        if (c + 2 < NCHUNK2) {
            cp_chunk2(sm + ((c + 2) % NSTAGE) * STAGE2_B, tid, tb, c + 2);
            asm volatile("cp.async.commit_group;" ::: "memory");
        }
    }

    // ---- stage logits to smem (alias over dead pipeline stages) ----
    float (*lg)[65] = (float (*)[65])sm;
#pragma unroll
    for (int mt = 0; mt < 2; ++mt) {
        const int r0 = wm * 32 + mt * 16 + gID;
#pragma unroll
        for (int nt = 0; nt < 4; ++nt) {
            const int e0 = wn * 32 + nt * 8 + tig * 2;
            lg[r0][e0]         = acc[mt][nt][0] * DS2;
            lg[r0][e0 + 1]     = acc[mt][nt][1] * DS2;
            lg[r0 + 8][e0]     = acc[mt][nt][2] * DS2;
            lg[r0 + 8][e0 + 1] = acc[mt][nt][3] * DS2;
        }
    }
    __syncthreads();

    if (tid < 128) {
        const int r = tid;
        const int n = nblk + r;

        float m1 = -1e30f; int i1 = 0;
#pragma unroll
        for (int e = 0; e < NE; e++) {
            float v = lg[r][e];
            if (v > m1) { m1 = v; i1 = e; }
        }
        float m2 = -1e30f; int i2 = 0;
#pragma unroll
        for (int e = 0; e < NE; e++) {
            if (e == i1) continue;
            float v = lg[r][e];
            if (v > m2) { m2 = v; i2 = e; }
        }
        float s = 0.f;
#pragma unroll
        for (int e = 0; e < NE; e++) s += expf(lg[r][e] - m1);
        const float inv = 1.0f / s;

        const float lo = 1e-9f, hi = 1.0f - 1e-9f;
        const float p1 = fminf(fmaxf(inv + lo, lo), hi);
        const float p2 = fminf(fmaxf(expf(m2 - m1) * inv + lo, lo), hi);
        const float rn = 1.0f / (p1 + p2);

        float* mask = out;
        float* ti   = out + (size_t)NTOK * NE;
        float* rp   = out + (size_t)NTOK * NE + (size_t)NTOK * 2;
        float* pr   = rp  + (size_t)NTOK * NE;

#pragma unroll
        for (int e = 0; e < NE; e++) {
            float v = expf(lg[r][e] - m1) * inv + lo;
            v = fminf(fmaxf(v, lo), hi);
            pr[(size_t)n * NE + e]   = v;
            mask[(size_t)n * NE + e] = (e == i1 || e == i2) ? 1.0f : 0.0f;
            rp[(size_t)n * NE + e]   = (e == i1) ? p1 * rn
                                     : (e == i2) ? p2 * rn : 0.0f;
        }
        ti[(size_t)n * 2 + 0] = (float)i1;
        ti[(size_t)n * 2 + 1] = (float)i2;
    }
}

// ---------------------------------------------------------------------------
extern "C" void kernel_launch(void* const* d_in, const int* in_sizes, int n_in,
                              void* d_out, int out_size)
{
    const float* inp = (const float*)d_in[0];   // [8,4096,1024]
    const float* cnd = (const float*)d_in[1];   // [8,4096,512]
    const float* W1  = (const float*)d_in[2];   // [3072,1536]
    const float* W2  = (const float*)d_in[3];   // [64,3072]
    float* out = (float*)d_out;

    cudaFuncSetAttribute(k_gemm1_mma, cudaFuncAttributeMaxDynamicSharedMemorySize, SMEM1_BYTES);
    cudaFuncSetAttribute(k_gemm2_mma, cudaFuncAttributeMaxDynamicSharedMemorySize, SMEM2_BYTES);

    dim3 gx(NCHUNK, 256);
    k_presplit_x<<<gx, 256>>>(inp, cnd);
    dim3 gw(NCHUNK, 24);
    k_presplit_w<<<gw, 256>>>(W1);
    k_presplit_w2<<<NCHUNK2, 256>>>(W2);

    dim3 g1(DH / 128, NTOK / 128);   // 24 x 256 CTAs
    k_gemm1_mma<<<g1, 256, SMEM1_BYTES>>>();
    k_gemm2_mma<<<NTOK / 128, 256, SMEM2_BYTES>>>(out);
}